// round 13
// baseline (speedup 1.0000x reference)
#include <cuda_runtime.h>
#include <cuda_fp16.h>
#include <math.h>
#include <stdint.h>

#define T_TOK 8192
#define DIM   2048
#define ODIM  2048
#define NE    8
#define BM    128
#define BN    128
#define BK    64            // halves per K chunk (128 B per row)
#define NC    (DIM / BK)    // 32 chunks
#define NCOL  (ODIM / BN)   // 16 col tiles
#define STAGE_BYTES ((BM + BN) * 128)       // 32KB
#define SMEM_SZ (1024 + 3 * STAGE_BYTES)    // 97KB -> 2 CTAs/SM

// ---------------- device scratch (replay-state invariant) ----------------
__device__ __half g_WfullT[(size_t)NE * ODIM * DIM];  // [e][o][d] fp16, k contiguous
__device__ __half g_Xperm[(size_t)T_TOK * DIM];       // permuted tokens fp16
__device__ int    g_gate[T_TOK];
__device__ float  g_tprob[T_TOK];
__device__ float  g_Psum[NE];                         // zeroed by scatperm after use
__device__ int    g_count[NE];                        // zeroed by gemm after use
__device__ int    g_fill[NE];                         // zeroed by gate before use
__device__ int    g_perm[T_TOK];
__device__ int    g_tilectr;                          // zeroed by gate before gemm

// ---------------- PTX helpers ----------------
__device__ __forceinline__ uint32_t smem_u32(const void* p) {
    uint32_t a;
    asm("{ .reg .u64 t; cvta.to.shared.u64 t, %1; cvt.u32.u64 %0, t; }" : "=r"(a) : "l"(p));
    return a;
}
#define SW128(off) ((off) ^ (((off) >> 3) & 0x70))
#define CP_ASYNC16(dst, src) \
    asm volatile("cp.async.cg.shared.global [%0], [%1], 16;" :: "r"(dst), "l"(src))
#define CP_COMMIT() asm volatile("cp.async.commit_group;")
#define CP_WAIT1()  asm volatile("cp.async.wait_group 1;")

__device__ __forceinline__ void ldsm_x4(uint32_t* r, uint32_t addr) {
    asm volatile("ldmatrix.sync.aligned.m8n8.x4.shared.b16 {%0,%1,%2,%3}, [%4];"
                 : "=r"(r[0]), "=r"(r[1]), "=r"(r[2]), "=r"(r[3]) : "r"(addr));
}
__device__ __forceinline__ void mma16816(float* d, const uint32_t* a, uint32_t b0, uint32_t b1) {
    asm volatile("mma.sync.aligned.m16n8k16.row.col.f32.f16.f16.f32 "
                 "{%0,%1,%2,%3},{%4,%5,%6,%7},{%8,%9},{%0,%1,%2,%3};"
                 : "+f"(d[0]), "+f"(d[1]), "+f"(d[2]), "+f"(d[3])
                 : "r"(a[0]), "r"(a[1]), "r"(a[2]), "r"(a[3]), "r"(b0), "r"(b1));
}

// ---------------- gating: one warp per token; block 0 zeroes g_fill + tile counter ----------------
__global__ void gate_k(const float* __restrict__ x, const float* __restrict__ gw) {
    __shared__ float sP[NE];
    __shared__ int   sC[NE];
    if (threadIdx.x < NE) {
        sP[threadIdx.x] = 0.f; sC[threadIdx.x] = 0;
        if (blockIdx.x == 0) g_fill[threadIdx.x] = 0;
    }
    if (blockIdx.x == 0 && threadIdx.x == 8) g_tilectr = 0;
    __syncthreads();
    int warp = threadIdx.x >> 5, lane = threadIdx.x & 31;
    int t = blockIdx.x * 8 + warp;
    const float*  xr = x + (size_t)t * DIM;
    const float4* g4 = (const float4*)gw;
    float acc[8] = {0.f,0.f,0.f,0.f,0.f,0.f,0.f,0.f};
    for (int d = lane; d < DIM; d += 32) {
        float xv = xr[d];
        float4 a = g4[d * 2];
        float4 b = g4[d * 2 + 1];
        acc[0] += xv * a.x; acc[1] += xv * a.y; acc[2] += xv * a.z; acc[3] += xv * a.w;
        acc[4] += xv * b.x; acc[5] += xv * b.y; acc[6] += xv * b.z; acc[7] += xv * b.w;
    }
#pragma unroll
    for (int e = 0; e < 8; e++)
#pragma unroll
        for (int off = 16; off; off >>= 1)
            acc[e] += __shfl_down_sync(0xffffffffu, acc[e], off);
    if (lane == 0) {
        float m = acc[0]; int best = 0;
        for (int e = 1; e < 8; e++) if (acc[e] > m) { m = acc[e]; best = e; }
        float p[8], s = 0.f;
        for (int e = 0; e < 8; e++) { p[e] = expf(acc[e] - m); s += p[e]; }
        float inv = 1.f / s;
        g_gate[t]  = best;
        g_tprob[t] = p[best] * inv;
        for (int e = 0; e < 8; e++) atomicAdd(&sP[e], p[e] * inv);
        atomicAdd(&sC[best], 1);
    }
    __syncthreads();
    if (threadIdx.x < NE) {
        atomicAdd(&g_Psum[threadIdx.x], sP[threadIdx.x]);
        atomicAdd(&g_count[threadIdx.x], sC[threadIdx.x]);
    }
}

// ---------------- fused scatter + permute; block 0 writes loss tail, zeroes g_Psum ----------------
__global__ void scatperm_k(const float* __restrict__ x, float* __restrict__ out) {
    __shared__ int sPos;
    int t = blockIdx.x;
    if (threadIdx.x == 0) {
        int e = g_gate[t];
        int off = 0;
#pragma unroll
        for (int i = 0; i < NE; i++) off += (i < e) ? g_count[i] : 0;
        int pos = off + atomicAdd(&g_fill[e], 1);
        g_perm[pos] = t;
        sPos = pos;
    }
    if (t == 0 && threadIdx.x == 32) {
        float tot = 0.f;
        for (int e = 0; e < NE; e++)
            tot += (g_Psum[e] / (float)T_TOK) * ((float)g_count[e] / (float)T_TOK);
        out[(size_t)T_TOK * ODIM] = (float)NE * tot;
        for (int e = 0; e < NE; e++) {
            out[(size_t)T_TOK * ODIM + 1 + e] = (float)g_count[e];
            g_Psum[e] = 0.f;
        }
    }
    __syncthreads();
    int pos = sPos;
    int c0 = threadIdx.x * 8;
    const float4* s = (const float4*)(x + (size_t)t * DIM + c0);
    float4 v0 = s[0], v1 = s[1];
    __half2 h[4];
    h[0] = __float22half2_rn(make_float2(v0.x, v0.y));
    h[1] = __float22half2_rn(make_float2(v0.z, v0.w));
    h[2] = __float22half2_rn(make_float2(v1.x, v1.y));
    h[3] = __float22half2_rn(make_float2(v1.z, v1.w));
    *(uint4*)(g_Xperm + (size_t)pos * DIM + c0) = *(uint4*)h;
}

// ---------------- PHM densify + transpose -> fp16 (unchanged) ----------------
__global__ __launch_bounds__(256) void wfullT_k(const float* __restrict__ rule,
                                                const float* __restrict__ W) {
    __shared__ float Ws[4][32][33];
    int bid = blockIdx.x;
    int e  = bid >> 8;
    int ti = (bid >> 4) & 15;
    int tj = bid & 15;
    int tid = threadIdx.x;
    int ii = tid >> 3;
    int jq = (tid & 7) << 2;
#pragma unroll
    for (int p = 0; p < 4; p++) {
        const float4 w = *(const float4*)(W + ((size_t)((e * 4 + p) * 512 + ti * 32 + ii) * 512 + tj * 32 + jq));
        Ws[p][jq + 0][ii] = w.x;
        Ws[p][jq + 1][ii] = w.y;
        Ws[p][jq + 2][ii] = w.z;
        Ws[p][jq + 3][ii] = w.w;
    }
    __syncthreads();
    int jj = tid >> 3, iq = (tid & 7) << 2;
    float w0 = Ws[0][jj][iq], w0b = Ws[0][jj][iq+1], w0c = Ws[0][jj][iq+2], w0d = Ws[0][jj][iq+3];
    float w1 = Ws[1][jj][iq], w1b = Ws[1][jj][iq+1], w1c = Ws[1][jj][iq+2], w1d = Ws[1][jj][iq+3];
    float w2 = Ws[2][jj][iq], w2b = Ws[2][jj][iq+1], w2c = Ws[2][jj][iq+2], w2d = Ws[2][jj][iq+3];
    float w3 = Ws[3][jj][iq], w3b = Ws[3][jj][iq+1], w3c = Ws[3][jj][iq+2], w3d = Ws[3][jj][iq+3];
#pragma unroll
    for (int a = 0; a < 4; a++) {
#pragma unroll
        for (int b = 0; b < 4; b++) {
            float r0 = rule[((e * 4 + 0) * 4 + a) * 4 + b];
            float r1 = rule[((e * 4 + 1) * 4 + a) * 4 + b];
            float r2 = rule[((e * 4 + 2) * 4 + a) * 4 + b];
            float r3 = rule[((e * 4 + 3) * 4 + a) * 4 + b];
            float o0 = r0 * w0  + r1 * w1  + r2 * w2  + r3 * w3;
            float o1 = r0 * w0b + r1 * w1b + r2 * w2b + r3 * w3b;
            float o2 = r0 * w0c + r1 * w1c + r2 * w2c + r3 * w3c;
            float o3 = r0 * w0d + r1 * w1d + r2 * w2d + r3 * w3d;
            __half2 h0 = __float22half2_rn(make_float2(o0, o1));
            __half2 h1 = __float22half2_rn(make_float2(o2, o3));
            __half* dst = g_WfullT + ((size_t)e * ODIM + b * 512 + tj * 32 + jj) * DIM
                        + a * 512 + ti * 32 + iq;
            *(__half2*)(dst)     = h0;
            *(__half2*)(dst + 2) = h1;
        }
    }
}

// ---------------- persistent HMMA fp16 grouped GEMM: dynamic tile counter ----------------
__global__ __launch_bounds__(256, 2) void gemm_k(const float* __restrict__ bias,
                                                 float* __restrict__ out) {
    extern __shared__ char smem[];
    int tid = threadIdx.x;

    // first CTA resets g_count for next replay's gate
    if (blockIdx.x == 0 && tid < NE) g_count[tid] = 0;

    // total row tiles (from g_fill == per-expert counts after scatperm)
    int nRT = 0;
#pragma unroll
    for (int i = 0; i < NE; i++) nRT += (g_fill[i] + BM - 1) / BM;
    int totalTiles = nRT * NCOL;

    int*   sTok  = (int*)smem;
    float* sPr   = (float*)(smem + 512);
    int*   sTile = (int*)(smem + 1016);
    uint32_t sbu = smem_u32(smem);

    int wid = tid >> 5, lane = tid & 31;
    int warp_m = wid >> 2, warp_n = wid & 3;
    int q = lane >> 3, r = lane & 7;
    int mA  = warp_m * 64 + r + ((q & 1) << 3);
    int kqa = (q >> 1) << 4;
    int nB  = warp_n * 32 + r + ((q >> 1) << 3);
    int kqb = (q & 1) << 4;
    int rowq = lane >> 2, colq = (lane & 3) << 1;

    while (true) {
        __syncthreads();   // protect sTok/sPr/sTile from previous iteration's readers
        if (tid == 0) *sTile = atomicAdd(&g_tilectr, 1);
        __syncthreads();
        int tnum = *sTile;
        if (tnum >= totalTiles) break;

        int rowT = tnum >> 4;            // row tile: consecutive tnum share A row-tile
        int colBase = (tnum & 15) * BN;

        // decode rowT -> (e, r0, nv)
        int e = 0, r0 = 0, nv = 0;
        {
            int rem = rowT, off = 0;
#pragma unroll
            for (int i = 0; i < NE; i++) {
                int c = g_fill[i];
                int nt = (c + BM - 1) / BM;
                if (rem >= 0 && rem < nt) { e = i; r0 = off + rem * BM; nv = min(BM, c - rem * BM); }
                rem -= nt;
                off += c;
            }
        }

        if (tid < BM) {
            int idx = r0 + tid; if (idx > T_TOK - 1) idx = T_TOK - 1;
            int t = g_perm[idx];
            sTok[tid] = t;
            sPr[tid]  = g_tprob[t];
        }
        __syncthreads();

        const __half* Abase = g_Xperm  + (size_t)r0 * DIM;
        const __half* Bbase = g_WfullT + ((size_t)e * ODIM + colBase) * DIM;

        auto load_chunk = [&](int c) {
            int s = c % 3;
            uint32_t sa = sbu + 1024 + s * STAGE_BYTES;
            uint32_t sb = sa + BM * 128;
            const __half* ga = Abase + c * BK;
            const __half* gb = Bbase + c * BK;
#pragma unroll
            for (int i = 0; i < 4; i++) {
                int u = tid + i * 256;
                int row = u >> 3, sub = u & 7;
                CP_ASYNC16(sa + SW128(row * 128 + sub * 16), ga + (size_t)row * DIM + sub * 8);
            }
#pragma unroll
            for (int i = 0; i < 4; i++) {
                int u = tid + i * 256;
                int row = u >> 3, sub = u & 7;
                CP_ASYNC16(sb + SW128(row * 128 + sub * 16), gb + (size_t)row * DIM + sub * 8);
            }
        };

        float acc[4][4][4];
#pragma unroll
        for (int i = 0; i < 4; i++)
#pragma unroll
            for (int j = 0; j < 4; j++)
#pragma unroll
                for (int k = 0; k < 4; k++) acc[i][j][k] = 0.f;

        load_chunk(0); CP_COMMIT();
        load_chunk(1); CP_COMMIT();

        for (int c = 0; c < NC; c++) {
            CP_WAIT1();
            __syncthreads();
            if (c + 2 < NC) load_chunk(c + 2);
            CP_COMMIT();

            uint32_t sa = sbu + 1024 + (c % 3) * STAGE_BYTES;
            uint32_t sb = sa + BM * 128;
#pragma unroll
            for (int step = 0; step < 4; step++) {
                uint32_t a[4][4];
#pragma unroll
                for (int mt = 0; mt < 4; mt++)
                    ldsm_x4(a[mt], sa + SW128((mA + mt * 16) * 128 + step * 32 + kqa));
                uint32_t bf[2][4];
#pragma unroll
                for (int np = 0; np < 2; np++)
                    ldsm_x4(bf[np], sb + SW128((nB + np * 16) * 128 + step * 32 + kqb));
#pragma unroll
                for (int mt = 0; mt < 4; mt++)
#pragma unroll
                    for (int nt = 0; nt < 4; nt++)
                        mma16816(acc[mt][nt], a[mt],
                                 bf[nt >> 1][(nt & 1) << 1], bf[nt >> 1][((nt & 1) << 1) + 1]);
            }
        }

        const float* bp = bias + e * ODIM + colBase;
#pragma unroll
        for (int mt = 0; mt < 4; mt++) {
#pragma unroll
            for (int half = 0; half < 2; half++) {
                int rl = warp_m * 64 + mt * 16 + rowq + half * 8;
                if (rl < nv) {
                    int t = sTok[rl];
                    float pr = sPr[rl];
                    float* op = out + (size_t)t * ODIM + colBase;
#pragma unroll
                    for (int nt = 0; nt < 4; nt++) {
                        int col = warp_n * 32 + nt * 8 + colq;
                        float2 b2 = *(const float2*)(bp + col);
                        float2 o;
                        o.x = (acc[mt][nt][half * 2 + 0] + b2.x) * pr;
                        o.y = (acc[mt][nt][half * 2 + 1] + b2.y) * pr;
                        *(float2*)(op + col) = o;
                    }
                }
            }
        }
    }
}

extern "C" void kernel_launch(void* const* d_in, const int* in_sizes, int n_in,
                              void* d_out, int out_size) {
    const float* x    = (const float*)d_in[0];
    const float* gw   = (const float*)d_in[1];
    const float* rule = (const float*)d_in[2];
    const float* W    = (const float*)d_in[3];
    const float* bias = (const float*)d_in[4];
    float* out = (float*)d_out;

    static cudaStream_t s1 = nullptr;
    static cudaEvent_t evF = nullptr, evJ = nullptr;
    if (!s1) {
        cudaStreamCreateWithFlags(&s1, cudaStreamNonBlocking);
        cudaEventCreateWithFlags(&evF, cudaEventDisableTiming);
        cudaEventCreateWithFlags(&evJ, cudaEventDisableTiming);
        cudaFuncSetAttribute(gemm_k, cudaFuncAttributeMaxDynamicSharedMemorySize, SMEM_SZ);
    }

    // fork wfullT (no dependencies) onto s1 at graph start
    cudaEventRecord(evF, 0);
    cudaStreamWaitEvent(s1, evF, 0);
    wfullT_k<<<2048, 256, 0, s1>>>(rule, W);
    cudaEventRecord(evJ, s1);

    // main chain: gate(+resets) -> scatperm(+loss tail)
    gate_k<<<1024, 256>>>(x, gw);
    scatperm_k<<<T_TOK, 256>>>(x, out);

    // join: GEMM needs WfullT
    cudaStreamWaitEvent(0, evJ, 0);
    gemm_k<<<296, 256, SMEM_SZ>>>(bias, out);   // persistent: 2 CTAs/SM
}

// round 14
// speedup vs baseline: 1.0908x; 1.0908x over previous
#include <cuda_runtime.h>
#include <cuda_fp16.h>
#include <math.h>
#include <stdint.h>

#define T_TOK 8192
#define DIM   2048
#define ODIM  2048
#define NE    8
#define BM    128
#define BN    128
#define BK    64            // halves per K chunk (128 B per row)
#define NC    (DIM / BK)    // 32 chunks
#define STAGE_BYTES ((BM + BN) * 128)       // 32KB
#define SMEM_SZ (1024 + 3 * STAGE_BYTES)    // 97KB -> 2 CTAs/SM

// ---------------- device scratch (replay-state invariant) ----------------
__device__ __half g_WfullT[(size_t)NE * ODIM * DIM];  // [e][o][d] fp16, k contiguous
__device__ __half g_Xperm[(size_t)T_TOK * DIM];       // permuted tokens fp16
__device__ int    g_gate[T_TOK];
__device__ float  g_tprob[T_TOK];
__device__ float  g_Psum[NE];                         // zeroed by scatperm after use
__device__ int    g_count[NE];                        // zeroed by gemm after use
__device__ int    g_fill[NE];                         // zeroed by gate before use
__device__ int    g_perm[T_TOK];

// ---------------- PTX helpers ----------------
__device__ __forceinline__ uint32_t smem_u32(const void* p) {
    uint32_t a;
    asm("{ .reg .u64 t; cvta.to.shared.u64 t, %1; cvt.u32.u64 %0, t; }" : "=r"(a) : "l"(p));
    return a;
}
#define SW128(off) ((off) ^ (((off) >> 3) & 0x70))
#define CP_ASYNC16(dst, src) \
    asm volatile("cp.async.cg.shared.global [%0], [%1], 16;" :: "r"(dst), "l"(src))
#define CP_COMMIT() asm volatile("cp.async.commit_group;")
#define CP_WAIT1()  asm volatile("cp.async.wait_group 1;")

__device__ __forceinline__ void ldsm_x4(uint32_t* r, uint32_t addr) {
    asm volatile("ldmatrix.sync.aligned.m8n8.x4.shared.b16 {%0,%1,%2,%3}, [%4];"
                 : "=r"(r[0]), "=r"(r[1]), "=r"(r[2]), "=r"(r[3]) : "r"(addr));
}
__device__ __forceinline__ void mma16816(float* d, const uint32_t* a, uint32_t b0, uint32_t b1) {
    asm volatile("mma.sync.aligned.m16n8k16.row.col.f32.f16.f16.f32 "
                 "{%0,%1,%2,%3},{%4,%5,%6,%7},{%8,%9},{%0,%1,%2,%3};"
                 : "+f"(d[0]), "+f"(d[1]), "+f"(d[2]), "+f"(d[3])
                 : "r"(a[0]), "r"(a[1]), "r"(a[2]), "r"(a[3]), "r"(b0), "r"(b1));
}

// ---------------- gating: one warp per token; block 0 zeroes g_fill ----------------
__global__ void gate_k(const float* __restrict__ x, const float* __restrict__ gw) {
    __shared__ float sP[NE];
    __shared__ int   sC[NE];
    if (threadIdx.x < NE) {
        sP[threadIdx.x] = 0.f; sC[threadIdx.x] = 0;
        if (blockIdx.x == 0) g_fill[threadIdx.x] = 0;
    }
    __syncthreads();
    int warp = threadIdx.x >> 5, lane = threadIdx.x & 31;
    int t = blockIdx.x * 8 + warp;
    const float*  xr = x + (size_t)t * DIM;
    const float4* g4 = (const float4*)gw;
    float acc[8] = {0.f,0.f,0.f,0.f,0.f,0.f,0.f,0.f};
    for (int d = lane; d < DIM; d += 32) {
        float xv = xr[d];
        float4 a = g4[d * 2];
        float4 b = g4[d * 2 + 1];
        acc[0] += xv * a.x; acc[1] += xv * a.y; acc[2] += xv * a.z; acc[3] += xv * a.w;
        acc[4] += xv * b.x; acc[5] += xv * b.y; acc[6] += xv * b.z; acc[7] += xv * b.w;
    }
#pragma unroll
    for (int e = 0; e < 8; e++)
#pragma unroll
        for (int off = 16; off; off >>= 1)
            acc[e] += __shfl_down_sync(0xffffffffu, acc[e], off);
    if (lane == 0) {
        float m = acc[0]; int best = 0;
        for (int e = 1; e < 8; e++) if (acc[e] > m) { m = acc[e]; best = e; }
        float p[8], s = 0.f;
        for (int e = 0; e < 8; e++) { p[e] = expf(acc[e] - m); s += p[e]; }
        float inv = 1.f / s;
        g_gate[t]  = best;
        g_tprob[t] = p[best] * inv;
        for (int e = 0; e < 8; e++) atomicAdd(&sP[e], p[e] * inv);
        atomicAdd(&sC[best], 1);
    }
    __syncthreads();
    if (threadIdx.x < NE) {
        atomicAdd(&g_Psum[threadIdx.x], sP[threadIdx.x]);
        atomicAdd(&g_count[threadIdx.x], sC[threadIdx.x]);
    }
}

// ---------------- fused scatter + permute; block 0 writes loss tail, zeroes g_Psum ----------------
__global__ void scatperm_k(const float* __restrict__ x, float* __restrict__ out) {
    __shared__ int sPos;
    int t = blockIdx.x;
    if (threadIdx.x == 0) {
        int e = g_gate[t];
        int off = 0;
#pragma unroll
        for (int i = 0; i < NE; i++) off += (i < e) ? g_count[i] : 0;
        int pos = off + atomicAdd(&g_fill[e], 1);
        g_perm[pos] = t;
        sPos = pos;
    }
    if (t == 0 && threadIdx.x == 32) {
        float tot = 0.f;
        for (int e = 0; e < NE; e++)
            tot += (g_Psum[e] / (float)T_TOK) * ((float)g_count[e] / (float)T_TOK);
        out[(size_t)T_TOK * ODIM] = (float)NE * tot;
        for (int e = 0; e < NE; e++) {
            out[(size_t)T_TOK * ODIM + 1 + e] = (float)g_count[e];
            g_Psum[e] = 0.f;
        }
    }
    __syncthreads();
    int pos = sPos;
    int c0 = threadIdx.x * 8;
    const float4* s = (const float4*)(x + (size_t)t * DIM + c0);
    float4 v0 = s[0], v1 = s[1];
    __half2 h[4];
    h[0] = __float22half2_rn(make_float2(v0.x, v0.y));
    h[1] = __float22half2_rn(make_float2(v0.z, v0.w));
    h[2] = __float22half2_rn(make_float2(v1.x, v1.y));
    h[3] = __float22half2_rn(make_float2(v1.z, v1.w));
    *(uint4*)(g_Xperm + (size_t)pos * DIM + c0) = *(uint4*)h;
}

// ---------------- PHM densify + transpose -> fp16 (unchanged) ----------------
__global__ __launch_bounds__(256) void wfullT_k(const float* __restrict__ rule,
                                                const float* __restrict__ W) {
    __shared__ float Ws[4][32][33];
    int bid = blockIdx.x;
    int e  = bid >> 8;
    int ti = (bid >> 4) & 15;
    int tj = bid & 15;
    int tid = threadIdx.x;
    int ii = tid >> 3;
    int jq = (tid & 7) << 2;
#pragma unroll
    for (int p = 0; p < 4; p++) {
        const float4 w = *(const float4*)(W + ((size_t)((e * 4 + p) * 512 + ti * 32 + ii) * 512 + tj * 32 + jq));
        Ws[p][jq + 0][ii] = w.x;
        Ws[p][jq + 1][ii] = w.y;
        Ws[p][jq + 2][ii] = w.z;
        Ws[p][jq + 3][ii] = w.w;
    }
    __syncthreads();
    int jj = tid >> 3, iq = (tid & 7) << 2;
    float w0 = Ws[0][jj][iq], w0b = Ws[0][jj][iq+1], w0c = Ws[0][jj][iq+2], w0d = Ws[0][jj][iq+3];
    float w1 = Ws[1][jj][iq], w1b = Ws[1][jj][iq+1], w1c = Ws[1][jj][iq+2], w1d = Ws[1][jj][iq+3];
    float w2 = Ws[2][jj][iq], w2b = Ws[2][jj][iq+1], w2c = Ws[2][jj][iq+2], w2d = Ws[2][jj][iq+3];
    float w3 = Ws[3][jj][iq], w3b = Ws[3][jj][iq+1], w3c = Ws[3][jj][iq+2], w3d = Ws[3][jj][iq+3];
#pragma unroll
    for (int a = 0; a < 4; a++) {
#pragma unroll
        for (int b = 0; b < 4; b++) {
            float r0 = rule[((e * 4 + 0) * 4 + a) * 4 + b];
            float r1 = rule[((e * 4 + 1) * 4 + a) * 4 + b];
            float r2 = rule[((e * 4 + 2) * 4 + a) * 4 + b];
            float r3 = rule[((e * 4 + 3) * 4 + a) * 4 + b];
            float o0 = r0 * w0  + r1 * w1  + r2 * w2  + r3 * w3;
            float o1 = r0 * w0b + r1 * w1b + r2 * w2b + r3 * w3b;
            float o2 = r0 * w0c + r1 * w1c + r2 * w2c + r3 * w3c;
            float o3 = r0 * w0d + r1 * w1d + r2 * w2d + r3 * w3d;
            __half2 h0 = __float22half2_rn(make_float2(o0, o1));
            __half2 h1 = __float22half2_rn(make_float2(o2, o3));
            __half* dst = g_WfullT + ((size_t)e * ODIM + b * 512 + tj * 32 + jj) * DIM
                        + a * 512 + ti * 32 + iq;
            *(__half2*)(dst)     = h0;
            *(__half2*)(dst + 2) = h1;
        }
    }
}

// ---------------- HMMA fp16 grouped GEMM: 128x128 tiles, 3-stage, 2 CTAs/SM (R12 + interleave) ----
__global__ __launch_bounds__(256, 2) void gemm_k(const float* __restrict__ bias,
                                                 float* __restrict__ out) {
    extern __shared__ char smem[];
    int tid = threadIdx.x;

    // CTA(0,0) resets g_count for next replay's gate
    if (blockIdx.x == 0 && blockIdx.y == 0 && tid < NE) g_count[tid] = 0;

    // derive (e, r0, nv) from g_fill (== per-expert counts after scatperm)
    int e = 0, r0 = 0, nv = 0;
    {
        int rem = blockIdx.x, off = 0;
        bool valid = false;
#pragma unroll
        for (int i = 0; i < NE; i++) {
            int c = g_fill[i];
            int nt = (c + BM - 1) / BM;
            if (!valid && rem < nt) {
                e = i; r0 = off + rem * BM; nv = min(BM, c - rem * BM); valid = true;
            }
            if (!valid) { rem -= nt; }
            off += c;
        }
        if (!valid) return;
    }

    int*   sTok = (int*)smem;
    float* sPr  = (float*)(smem + 512);
    uint32_t sbu = smem_u32(smem);

    int colBase = blockIdx.y * BN;
    int wid = tid >> 5, lane = tid & 31;
    int warp_m = wid >> 2, warp_n = wid & 3;

    if (tid < BM) {
        int idx = r0 + tid; if (idx > T_TOK - 1) idx = T_TOK - 1;
        int t = g_perm[idx];
        sTok[tid] = t;
        sPr[tid]  = g_tprob[t];
    }
    __syncthreads();

    const __half* Abase = g_Xperm  + (size_t)r0 * DIM;
    const __half* Bbase = g_WfullT + ((size_t)e * ODIM + colBase) * DIM;

    auto load_chunk = [&](int c) {
        int s = c % 3;
        uint32_t sa = sbu + 1024 + s * STAGE_BYTES;
        uint32_t sb = sa + BM * 128;
        const __half* ga = Abase + c * BK;
        const __half* gb = Bbase + c * BK;
#pragma unroll
        for (int i = 0; i < 4; i++) {
            int u = tid + i * 256;
            int row = u >> 3, sub = u & 7;
            CP_ASYNC16(sa + SW128(row * 128 + sub * 16), ga + (size_t)row * DIM + sub * 8);
        }
#pragma unroll
        for (int i = 0; i < 4; i++) {
            int u = tid + i * 256;
            int row = u >> 3, sub = u & 7;
            CP_ASYNC16(sb + SW128(row * 128 + sub * 16), gb + (size_t)row * DIM + sub * 8);
        }
    };

    float acc[4][4][4];
#pragma unroll
    for (int i = 0; i < 4; i++)
#pragma unroll
        for (int j = 0; j < 4; j++)
#pragma unroll
            for (int k = 0; k < 4; k++) acc[i][j][k] = 0.f;

    int q = lane >> 3, r = lane & 7;
    int mA  = warp_m * 64 + r + ((q & 1) << 3);
    int kqa = (q >> 1) << 4;
    int nB  = warp_n * 32 + r + ((q >> 1) << 3);
    int kqb = (q & 1) << 4;

    load_chunk(0); CP_COMMIT();
    load_chunk(1); CP_COMMIT();

    for (int c = 0; c < NC; c++) {
        CP_WAIT1();
        __syncthreads();
        if (c + 2 < NC) load_chunk(c + 2);
        CP_COMMIT();

        uint32_t sa = sbu + 1024 + (c % 3) * STAGE_BYTES;
        uint32_t sb = sa + BM * 128;
#pragma unroll
        for (int step = 0; step < 4; step++) {
            // B fragments first, then per-mt: one A ldsm followed immediately by its MMAs
            uint32_t bf[2][4];
#pragma unroll
            for (int np = 0; np < 2; np++)
                ldsm_x4(bf[np], sb + SW128((nB + np * 16) * 128 + step * 32 + kqb));
#pragma unroll
            for (int mt = 0; mt < 4; mt++) {
                uint32_t a[4];
                ldsm_x4(a, sa + SW128((mA + mt * 16) * 128 + step * 32 + kqa));
#pragma unroll
                for (int nt = 0; nt < 4; nt++)
                    mma16816(acc[mt][nt], a,
                             bf[nt >> 1][(nt & 1) << 1], bf[nt >> 1][((nt & 1) << 1) + 1]);
            }
        }
    }

    int rowq = lane >> 2, colq = (lane & 3) << 1;
    const float* bp = bias + e * ODIM + colBase;
#pragma unroll
    for (int mt = 0; mt < 4; mt++) {
#pragma unroll
        for (int half = 0; half < 2; half++) {
            int rl = warp_m * 64 + mt * 16 + rowq + half * 8;
            if (rl < nv) {
                int t = sTok[rl];
                float pr = sPr[rl];
                float* op = out + (size_t)t * ODIM + colBase;
#pragma unroll
                for (int nt = 0; nt < 4; nt++) {
                    int col = warp_n * 32 + nt * 8 + colq;
                    float2 b2 = *(const float2*)(bp + col);
                    float2 o;
                    o.x = (acc[mt][nt][half * 2 + 0] + b2.x) * pr;
                    o.y = (acc[mt][nt][half * 2 + 1] + b2.y) * pr;
                    *(float2*)(op + col) = o;
                }
            }
        }
    }
}

extern "C" void kernel_launch(void* const* d_in, const int* in_sizes, int n_in,
                              void* d_out, int out_size) {
    const float* x    = (const float*)d_in[0];
    const float* gw   = (const float*)d_in[1];
    const float* rule = (const float*)d_in[2];
    const float* W    = (const float*)d_in[3];
    const float* bias = (const float*)d_in[4];
    float* out = (float*)d_out;

    static cudaStream_t s1 = nullptr;
    static cudaEvent_t evF = nullptr, evJ = nullptr;
    if (!s1) {
        cudaStreamCreateWithFlags(&s1, cudaStreamNonBlocking);
        cudaEventCreateWithFlags(&evF, cudaEventDisableTiming);
        cudaEventCreateWithFlags(&evJ, cudaEventDisableTiming);
        cudaFuncSetAttribute(gemm_k, cudaFuncAttributeMaxDynamicSharedMemorySize, SMEM_SZ);
    }

    // fork wfullT (no dependencies) onto s1 at graph start
    cudaEventRecord(evF, 0);
    cudaStreamWaitEvent(s1, evF, 0);
    wfullT_k<<<2048, 256, 0, s1>>>(rule, W);
    cudaEventRecord(evJ, s1);

    // main chain: gate(+fill reset) -> scatperm(+loss tail)
    gate_k<<<1024, 256>>>(x, gw);
    scatperm_k<<<T_TOK, 256>>>(x, out);

    // join: GEMM needs WfullT
    cudaStreamWaitEvent(0, evJ, 0);
    dim3 grid(72, ODIM / BN);
    gemm_k<<<grid, 256, SMEM_SZ>>>(bias, out);
}